// round 1
// baseline (speedup 1.0000x reference)
#include <cuda_runtime.h>
#include <cstdint>

// Problem dims (fixed by reference)
#define BB 8
#define TT 2048
#define CC 1024
#define DD 64
#define ROWS (BB*TT)      // 16384
#define S_SPLIT 4
#define QB 128            // queries per attention block
#define KT 32             // key tile in smem

// Scratch (allocation-free: __device__ globals)
__device__ float g_q[ROWS*DD];
__device__ float g_k[ROWS*DD];
__device__ float g_v[ROWS*DD];
__device__ float g_po[S_SPLIT*ROWS*DD];
__device__ float g_pm[S_SPLIT*ROWS];
__device__ float g_pl[S_SPLIT*ROWS];

typedef unsigned long long u64;

__device__ __forceinline__ u64 pack2(float lo, float hi){
  u64 r; asm("mov.b64 %0,{%1,%2};" : "=l"(r) : "f"(lo), "f"(hi)); return r;
}
__device__ __forceinline__ void unpack2(u64 v, float &lo, float &hi){
  asm("mov.b64 {%0,%1},%2;" : "=f"(lo), "=f"(hi) : "l"(v));
}
__device__ __forceinline__ u64 ffma2(u64 a, u64 b, u64 c){
  u64 d; asm("fma.rn.f32x2 %0,%1,%2,%3;" : "=l"(d) : "l"(a), "l"(b), "l"(c)); return d;
}
__device__ __forceinline__ u64 fmul2(u64 a, u64 b){
  u64 d; asm("mul.rn.f32x2 %0,%1,%2;" : "=l"(d) : "l"(a), "l"(b)); return d;
}
__device__ __forceinline__ u64 fadd2(u64 a, u64 b){
  u64 d; asm("add.rn.f32x2 %0,%1,%2;" : "=l"(d) : "l"(a), "l"(b)); return d;
}

// ---------------------------------------------------------------------------
// Kernel 1: fused QKV projection. grid = (ROWS/128, 3), 256 threads.
// out[row, :] = x[row, :] @ W  (W: [1024, 64]); blockIdx.y selects K/Q/V.
// BM=128, BN=64, BK=16; per-thread 8x4 microtile, f32x2 paired over rows.
// ---------------------------------------------------------------------------
__global__ __launch_bounds__(256) void proj_kernel(
    const float* __restrict__ x,
    const float* __restrict__ Wk,
    const float* __restrict__ Wq,
    const float* __restrict__ Wv)
{
  const int BM = 128, BK = 16;
  __shared__ float xs[BK][BM];   // x tile, transposed [k][row]
  __shared__ float ws[BK][DD];   // W tile [k][col]

  const float* W  = (blockIdx.y == 0) ? Wk : ((blockIdx.y == 1) ? Wq : Wv);
  float*       out = (blockIdx.y == 0) ? g_k : ((blockIdx.y == 1) ? g_q : g_v);

  const int rowBase = blockIdx.x * BM;
  const int t  = threadIdx.x;
  const int ty = t >> 4;     // 0..15 -> rows ty*8 .. ty*8+7
  const int tx = t & 15;     // 0..15 -> cols tx*4 .. tx*4+3

  u64 acc[4][4];             // [row-pair][col]
  #pragma unroll
  for (int i = 0; i < 4; i++)
    #pragma unroll
    for (int c = 0; c < 4; c++) acc[i][c] = pack2(0.f, 0.f);

  for (int k0 = 0; k0 < CC; k0 += BK) {
    // load x tile (transposed into smem)
    #pragma unroll
    for (int i = 0; i < 2; i++) {
      int idx = t + i * 256;            // 0..511
      int row = idx >> 2;               // 0..127
      int kc  = (idx & 3) << 2;         // 0,4,8,12
      float4 v4 = *(const float4*)(x + (size_t)(rowBase + row) * CC + k0 + kc);
      xs[kc + 0][row] = v4.x;
      xs[kc + 1][row] = v4.y;
      xs[kc + 2][row] = v4.z;
      xs[kc + 3][row] = v4.w;
    }
    // load W tile
    {
      int wrow = t >> 4;                // 0..15
      int wc   = (t & 15) << 2;         // 0..60
      *(float4*)&ws[wrow][wc] = *(const float4*)(W + (size_t)(k0 + wrow) * DD + wc);
    }
    __syncthreads();

    #pragma unroll
    for (int kk = 0; kk < BK; kk++) {
      ulonglong2 a01 = *(const ulonglong2*)&xs[kk][ty * 8];
      ulonglong2 a23 = *(const ulonglong2*)&xs[kk][ty * 8 + 4];
      u64 ap[4] = { a01.x, a01.y, a23.x, a23.y };
      #pragma unroll
      for (int c = 0; c < 4; c++) {
        float bv = ws[kk][tx * 4 + c];
        u64 b2 = pack2(bv, bv);
        #pragma unroll
        for (int i = 0; i < 4; i++) acc[i][c] = ffma2(ap[i], b2, acc[i][c]);
      }
    }
    __syncthreads();
  }

  // store 8 rows x 4 cols
  #pragma unroll
  for (int i = 0; i < 4; i++) {
    float lo[4], hi[4];
    #pragma unroll
    for (int c = 0; c < 4; c++) unpack2(acc[i][c], lo[c], hi[c]);
    int r0 = rowBase + ty * 8 + 2 * i;
    *(float4*)(out + (size_t)r0       * DD + tx * 4) = make_float4(lo[0], lo[1], lo[2], lo[3]);
    *(float4*)(out + (size_t)(r0 + 1) * DD + tx * 4) = make_float4(hi[0], hi[1], hi[2], hi[3]);
  }
}

// ---------------------------------------------------------------------------
// Kernel 2: flash attention with 4-way global split-KV.
// grid = (T/QB, B, S_SPLIT), 128 threads. Thread tid owns query row qb*128+tid.
// Writes unnormalized partial (m, l, o) per split.
// ---------------------------------------------------------------------------
__global__ __launch_bounds__(128) void attn_kernel()
{
  __shared__ float ks_s[KT * DD];
  __shared__ float vs_s[KT * DD];

  const int qb  = blockIdx.x;
  const int b   = blockIdx.y;
  const int sp  = blockIdx.z;
  const int tid = threadIdx.x;

  const int t   = qb * QB + tid;       // query position in sequence
  const int row = b * TT + t;          // global row

  // causal kv length for this q-block, split into S_SPLIT ranges (mult. of 32)
  const int chunk = (qb + 1) * (QB / S_SPLIT);
  const int ks0 = sp * chunk;
  const int ke  = ks0 + chunk;

  // q row in registers, pre-scaled by d^-0.5 = 0.125
  u64 q2[32];
  {
    const float* qp = g_q + (size_t)row * DD;
    #pragma unroll
    for (int i = 0; i < 16; i++) {
      float4 v4 = *(const float4*)(qp + i * 4);
      q2[2 * i]     = pack2(v4.x * 0.125f, v4.y * 0.125f);
      q2[2 * i + 1] = pack2(v4.z * 0.125f, v4.w * 0.125f);
    }
  }

  u64 o2[32];
  #pragma unroll
  for (int i = 0; i < 32; i++) o2[i] = pack2(0.f, 0.f);
  float m = -__int_as_float(0x7f800000);   // -inf... careful: use bit pattern directly
  m = __int_as_float(0xff800000);          // -inf
  float l = 0.f;

  for (int kt = ks0; kt < ke; kt += KT) {
    __syncthreads();
    // cooperative K/V tile load: 32 rows x 64 cols each
    #pragma unroll
    for (int i = 0; i < 4; i++) {
      int idx = tid + i * 128;           // 0..511
      int kr  = idx >> 4;                // 0..31
      int kc  = (idx & 15) << 2;         // 0..60
      size_t g = ((size_t)(b * TT + kt + kr)) * DD + kc;
      *(float4*)&ks_s[kr * DD + kc] = *(const float4*)(g_k + g);
      *(float4*)&vs_s[kr * DD + kc] = *(const float4*)(g_v + g);
    }
    __syncthreads();

    int jmax = t - kt + 1;               // keys kt+j valid iff kt+j <= t
    if (jmax > KT) jmax = KT;
    for (int j = 0; j < jmax; j++) {
      // s = q . k_j  (f32x2, 4 accumulators)
      const ulonglong2* kr2 = (const ulonglong2*)&ks_s[j * DD];
      u64 a0 = pack2(0.f, 0.f), a1 = a0, a2 = a0, a3 = a0;
      #pragma unroll
      for (int i = 0; i < 8; i++) {
        ulonglong2 kA = kr2[2 * i];
        ulonglong2 kB = kr2[2 * i + 1];
        a0 = ffma2(q2[4 * i + 0], kA.x, a0);
        a1 = ffma2(q2[4 * i + 1], kA.y, a1);
        a2 = ffma2(q2[4 * i + 2], kB.x, a2);
        a3 = ffma2(q2[4 * i + 3], kB.y, a3);
      }
      u64 asum = fadd2(fadd2(a0, a1), fadd2(a2, a3));
      float slo, shi; unpack2(asum, slo, shi);
      float s = slo + shi;

      // online softmax
      float m_new = fmaxf(m, s);
      float p = __expf(s - m_new);
      if (m_new > m) {
        float corr = __expf(m - m_new);  // exp(-inf)=0 on first key: o already 0
        u64 c2 = pack2(corr, corr);
        l *= corr;
        #pragma unroll
        for (int i = 0; i < 32; i++) o2[i] = fmul2(o2[i], c2);
        m = m_new;
      }
      l += p;

      u64 p2 = pack2(p, p);
      const ulonglong2* vr2 = (const ulonglong2*)&vs_s[j * DD];
      #pragma unroll
      for (int i = 0; i < 16; i++) {
        ulonglong2 vv = vr2[i];
        o2[2 * i]     = ffma2(p2, vv.x, o2[2 * i]);
        o2[2 * i + 1] = ffma2(p2, vv.y, o2[2 * i + 1]);
      }
    }
  }

  // write partials (unnormalized)
  size_t pr = (size_t)sp * ROWS + row;
  g_pm[pr] = m;
  g_pl[pr] = l;
  float* po = g_po + pr * (size_t)DD;
  #pragma unroll
  for (int i = 0; i < 32; i++) *(u64*)(po + 2 * i) = o2[i];
}

// ---------------------------------------------------------------------------
// Kernel 3: LSE combine across splits + final normalization.
// grid = ROWS/256, 256 threads; one thread per output row.
// ---------------------------------------------------------------------------
__global__ __launch_bounds__(256) void combine_kernel(float* __restrict__ out)
{
  int r = blockIdx.x * blockDim.x + threadIdx.x;

  float m[S_SPLIT], l[S_SPLIT];
  #pragma unroll
  for (int s = 0; s < S_SPLIT; s++) {
    m[s] = g_pm[(size_t)s * ROWS + r];
    l[s] = g_pl[(size_t)s * ROWS + r];
  }
  float M = fmaxf(fmaxf(m[0], m[1]), fmaxf(m[2], m[3]));
  float w[S_SPLIT]; float L = 0.f;
  #pragma unroll
  for (int s = 0; s < S_SPLIT; s++) { w[s] = __expf(m[s] - M); L += l[s] * w[s]; }
  float inv = 1.0f / L;

  #pragma unroll
  for (int i = 0; i < 16; i++) {
    float4 acc = make_float4(0.f, 0.f, 0.f, 0.f);
    #pragma unroll
    for (int s = 0; s < S_SPLIT; s++) {
      float4 p = *(const float4*)(g_po + ((size_t)s * ROWS + r) * DD + i * 4);
      acc.x += p.x * w[s]; acc.y += p.y * w[s];
      acc.z += p.z * w[s]; acc.w += p.w * w[s];
    }
    acc.x *= inv; acc.y *= inv; acc.z *= inv; acc.w *= inv;
    *(float4*)(out + (size_t)r * DD + i * 4) = acc;
  }
}

// ---------------------------------------------------------------------------
extern "C" void kernel_launch(void* const* d_in, const int* in_sizes, int n_in,
                              void* d_out, int out_size)
{
  const float* x  = (const float*)d_in[0];
  const float* Wk = (const float*)d_in[1];
  const float* Wq = (const float*)d_in[2];
  const float* Wv = (const float*)d_in[3];
  float* out = (float*)d_out;

  proj_kernel<<<dim3(ROWS / 128, 3), 256>>>(x, Wk, Wq, Wv);
  attn_kernel<<<dim3(TT / QB, BB, S_SPLIT), 128>>>();
  combine_kernel<<<ROWS / 256, 256>>>(out);
}